// round 1
// baseline (speedup 1.0000x reference)
#include <cuda_runtime.h>
#include <math.h>

#define NN 100000
#define EE 1600000
#define TEC (EE + NN)
#define BIGF 1e30f

// ---------------- scratch (static __device__ per harness rules) ----------------
__device__ float g_h1[NN * 64];
__device__ float g_out1[NN * 64];
__device__ float g_h2[NN * 40];
__device__ float g_a1s[NN * 8];
__device__ float g_a1d[NN * 8];
__device__ float g_a2s[NN];
__device__ float g_a2d[NN];
__device__ int   g_counts[NN];
__device__ int   g_rowptr[NN + 1];
__device__ int   g_cursor[NN];
__device__ int   g_src32[EE];
__device__ int   g_dst32[EE];
__device__ int   g_csr[TEC];
__device__ int   g_bsum[128];
__device__ int   g_flag;

// ---------------- edge dtype detection (int64 vs int32) ----------------
// If data is int64 (values < 2^17), every odd 32-bit word is zero.
__global__ void k_detect(const unsigned* __restrict__ u) {
    int t = threadIdx.x;
    unsigned v = 0;
    for (int i = t; i < 128; i += 32) v |= u[2 * i + 1];
    unsigned any = __ballot_sync(0xffffffffu, v != 0u);
    if (t == 0) g_flag = (any == 0u) ? 1 : 0;
}

__global__ void k_convert(const void* __restrict__ ei, int E) {
    int e = blockIdx.x * blockDim.x + threadIdx.x;
    if (e >= E) return;
    if (g_flag) {
        const long long* p = (const long long*)ei;
        g_src32[e] = (int)p[e];
        g_dst32[e] = (int)p[E + e];
    } else {
        const int* p = (const int*)ei;
        g_src32[e] = p[e];
        g_dst32[e] = p[E + e];
    }
}

// ---------------- CSR build ----------------
__global__ void k_init(int N) {
    int i = blockIdx.x * blockDim.x + threadIdx.x;
    if (i < N) g_counts[i] = 1;  // self-loop
}

__global__ void k_hist(int E) {
    int e = blockIdx.x * blockDim.x + threadIdx.x;
    if (e < E) atomicAdd(&g_counts[g_dst32[e]], 1);
}

__global__ void k_bsum(int N) {
    __shared__ int sm[1024];
    int i = blockIdx.x * 1024 + threadIdx.x;
    sm[threadIdx.x] = (i < N) ? g_counts[i] : 0;
    __syncthreads();
    for (int s = 512; s > 0; s >>= 1) {
        if (threadIdx.x < s) sm[threadIdx.x] += sm[threadIdx.x + s];
        __syncthreads();
    }
    if (threadIdx.x == 0) g_bsum[blockIdx.x] = sm[0];
}

__global__ void k_scanb(int nb) {
    __shared__ int sm[128];
    int t = threadIdx.x;
    int v = (t < nb) ? g_bsum[t] : 0;
    sm[t] = v;
    __syncthreads();
    for (int off = 1; off < 128; off <<= 1) {
        int u = (t >= off) ? sm[t - off] : 0;
        __syncthreads();
        sm[t] += u;
        __syncthreads();
    }
    if (t < nb) g_bsum[t] = sm[t] - v;  // exclusive
}

__global__ void k_scanf(int N) {
    __shared__ int sm[1024];
    int t = threadIdx.x;
    int i = blockIdx.x * 1024 + t;
    int v = (i < N) ? g_counts[i] : 0;
    sm[t] = v;
    __syncthreads();
    for (int off = 1; off < 1024; off <<= 1) {
        int u = (t >= off) ? sm[t - off] : 0;
        __syncthreads();
        sm[t] += u;
        __syncthreads();
    }
    int excl = sm[t] - v + g_bsum[blockIdx.x];
    if (i < N) { g_rowptr[i] = excl; g_cursor[i] = excl; }
    if (i == N - 1) g_rowptr[N] = excl + v;
}

__global__ void k_scatter(int E, int N) {
    int e = blockIdx.x * blockDim.x + threadIdx.x;
    if (e >= E + N) return;
    int s, d;
    if (e < E) { s = g_src32[e]; d = g_dst32[e]; }
    else       { s = e - E; d = s; }
    int pos = atomicAdd(&g_cursor[d], 1);
    g_csr[pos] = s;
}

// ---------------- GEMM1: h1 = x @ W1  (K=128, Nout=64) ----------------
__global__ void k_gemm1(const float* __restrict__ x, const float* __restrict__ W, int N) {
    __shared__ float xs[64][68];
    __shared__ float ws[64][68];
    int t = threadIdx.x;
    int r0 = blockIdx.x * 64;
    int tx = t & 15, ty = t >> 4;
    float acc[4][4];
#pragma unroll
    for (int i = 0; i < 4; ++i)
#pragma unroll
        for (int j = 0; j < 4; ++j) acc[i][j] = 0.f;

    for (int kt = 0; kt < 2; ++kt) {
#pragma unroll
        for (int p = 0; p < 4; ++p) {
            int row = ty + p * 16;
            int col4 = tx * 4;
            int gr = r0 + row;
            float4 v = make_float4(0.f, 0.f, 0.f, 0.f);
            if (gr < N) v = *(const float4*)&x[(size_t)gr * 128 + kt * 64 + col4];
            *(float4*)&xs[row][col4] = v;
            float4 wv = *(const float4*)&W[(size_t)(kt * 64 + row) * 64 + col4];
            *(float4*)&ws[row][col4] = wv;
        }
        __syncthreads();
#pragma unroll 16
        for (int k = 0; k < 64; ++k) {
            float4 b = *(const float4*)&ws[k][tx * 4];
            float a0 = xs[ty * 4 + 0][k];
            float a1 = xs[ty * 4 + 1][k];
            float a2 = xs[ty * 4 + 2][k];
            float a3 = xs[ty * 4 + 3][k];
            acc[0][0] += a0 * b.x; acc[0][1] += a0 * b.y; acc[0][2] += a0 * b.z; acc[0][3] += a0 * b.w;
            acc[1][0] += a1 * b.x; acc[1][1] += a1 * b.y; acc[1][2] += a1 * b.z; acc[1][3] += a1 * b.w;
            acc[2][0] += a2 * b.x; acc[2][1] += a2 * b.y; acc[2][2] += a2 * b.z; acc[2][3] += a2 * b.w;
            acc[3][0] += a3 * b.x; acc[3][1] += a3 * b.y; acc[3][2] += a3 * b.z; acc[3][3] += a3 * b.w;
        }
        __syncthreads();
    }
#pragma unroll
    for (int i = 0; i < 4; ++i) {
        int gr = r0 + ty * 4 + i;
        if (gr < N)
            *(float4*)&g_h1[(size_t)gr * 64 + tx * 4] =
                make_float4(acc[i][0], acc[i][1], acc[i][2], acc[i][3]);
    }
}

// ---------------- attention scalars layer 1 ----------------
__global__ void k_att1(const float* __restrict__ as, const float* __restrict__ ad, int N) {
    int t = blockIdx.x * blockDim.x + threadIdx.x;
    if (t >= N * 8) return;
    int h = t & 7;
    const float* hp = &g_h1[(size_t)t * 8];
    float s = 0.f, dd = 0.f;
#pragma unroll
    for (int c = 0; c < 8; ++c) {
        float v = hp[c];
        s += v * as[h * 8 + c];
        dd += v * ad[h * 8 + c];
    }
    g_a1s[t] = s;
    g_a1d[t] = dd;
}

// ---------------- layer-1 softmax + aggregation + bias + ELU ----------------
__global__ void k_agg1(const float* __restrict__ b1, int N) {
    int warp = threadIdx.x >> 5;
    int lane = threadIdx.x & 31;
    int d = blockIdx.x * 8 + warp;
    if (d >= N) return;
    int rs = g_rowptr[d], re = g_rowptr[d + 1];
    int h = lane & 7;
    float adst = g_a1d[d * 8 + h];

    // pass 1: per-head max (4 edge slots x 8 heads per lane layout)
    float m = -BIGF;
    for (int i = rs + (lane >> 3); i < re; i += 4) {
        int s = g_csr[i];
        float e = g_a1s[s * 8 + h] + adst;
        e = (e > 0.f) ? e : 0.2f * e;
        m = fmaxf(m, e);
    }
    m = fmaxf(m, __shfl_xor_sync(0xffffffffu, m, 8));
    m = fmaxf(m, __shfl_xor_sync(0xffffffffu, m, 16));

    // pass 2: weights + message accumulation (lane owns cols lane, lane+32)
    float wsum = 0.f, acc0 = 0.f, acc1 = 0.f;
    int hs0 = lane >> 3, hs1 = hs0 + 4;  // source lanes holding w for heads c/8
    for (int i = rs; i < re; ++i) {
        int s = g_csr[i];
        float e = g_a1s[s * 8 + h] + adst;
        e = (e > 0.f) ? e : 0.2f * e;
        float w = __expf(e - m);
        wsum += w;
        float w0 = __shfl_sync(0xffffffffu, w, hs0);
        float w1 = __shfl_sync(0xffffffffu, w, hs1);
        const float* hp = &g_h1[(size_t)s * 64];
        acc0 += w0 * hp[lane];
        acc1 += w1 * hp[lane + 32];
    }
    float d0 = __shfl_sync(0xffffffffu, wsum, hs0) + 1e-16f;
    float d1 = __shfl_sync(0xffffffffu, wsum, hs1) + 1e-16f;
    float o0 = acc0 / d0 + b1[lane];
    float o1 = acc1 / d1 + b1[lane + 32];
    o0 = (o0 > 0.f) ? o0 : (__expf(o0) - 1.f);   // ELU
    o1 = (o1 > 0.f) ? o1 : (__expf(o1) - 1.f);
    g_out1[(size_t)d * 64 + lane] = o0;
    g_out1[(size_t)d * 64 + lane + 32] = o1;
}

// ---------------- GEMM2: h2 = out1 @ W2 (K=64, Nout=40) + fused att2 ----------------
__global__ void k_gemm2(const float* __restrict__ W2, const float* __restrict__ as2,
                        const float* __restrict__ ad2, int N) {
    __shared__ float xs[64][68];
    __shared__ float ws[64][40];
    __shared__ float sa[40], sd[40];
    int t = threadIdx.x;
    int r0 = blockIdx.x * 64;
    for (int i = t; i < 64 * 40; i += 256) ws[i / 40][i % 40] = W2[i];
    if (t < 40) { sa[t] = as2[t]; sd[t] = ad2[t]; }
#pragma unroll
    for (int p = 0; p < 4; ++p) {
        int idx = t + p * 256;
        int row = idx >> 4;
        int col4 = (idx & 15) * 4;
        int gr = r0 + row;
        float4 v = make_float4(0.f, 0.f, 0.f, 0.f);
        if (gr < N) v = *(const float4*)&g_out1[(size_t)gr * 64 + col4];
        *(float4*)&xs[row][col4] = v;
    }
    __syncthreads();
    int row = t >> 2, g = t & 3;
    int gr = r0 + row;
    float acc[10];
#pragma unroll
    for (int j = 0; j < 10; ++j) acc[j] = 0.f;
#pragma unroll 8
    for (int k = 0; k < 64; ++k) {
        float a = xs[row][k];
#pragma unroll
        for (int j = 0; j < 10; ++j) acc[j] += a * ws[k][g * 10 + j];
    }
    float ps = 0.f, pd = 0.f;
    if (gr < N) {
#pragma unroll
        for (int j = 0; j < 10; ++j) {
            g_h2[(size_t)gr * 40 + g * 10 + j] = acc[j];
            ps += acc[j] * sa[g * 10 + j];
            pd += acc[j] * sd[g * 10 + j];
        }
    }
    ps += __shfl_xor_sync(0xffffffffu, ps, 1);
    ps += __shfl_xor_sync(0xffffffffu, ps, 2);
    pd += __shfl_xor_sync(0xffffffffu, pd, 1);
    pd += __shfl_xor_sync(0xffffffffu, pd, 2);
    if (g == 0 && gr < N) { g_a2s[gr] = ps; g_a2d[gr] = pd; }
}

// ---------------- layer-2 softmax + aggregation + bias + log_softmax ----------------
__global__ void k_agg2(const float* __restrict__ b2, float* __restrict__ out, int N) {
    int warp = threadIdx.x >> 5, lane = threadIdx.x & 31;
    int d = blockIdx.x * 8 + warp;
    if (d >= N) return;
    int rs = g_rowptr[d], re = g_rowptr[d + 1];
    float adst = g_a2d[d];

    float m = -BIGF;
    for (int i = rs + lane; i < re; i += 32) {
        float e = g_a2s[g_csr[i]] + adst;
        e = (e > 0.f) ? e : 0.2f * e;
        m = fmaxf(m, e);
    }
    for (int o = 16; o; o >>= 1) m = fmaxf(m, __shfl_xor_sync(0xffffffffu, m, o));

    float wsum = 0.f, acc0 = 0.f, acc1 = 0.f;
    for (int i = rs; i < re; ++i) {
        int s = g_csr[i];
        float e = g_a2s[s] + adst;
        e = (e > 0.f) ? e : 0.2f * e;
        float w = __expf(e - m);
        wsum += w;
        const float* hp = &g_h2[(size_t)s * 40];
        acc0 += w * hp[lane];
        if (lane < 8) acc1 += w * hp[lane + 32];
    }
    float inv = 1.f / (wsum + 1e-16f);
    float v0 = acc0 * inv + b2[lane];
    float v1 = (lane < 8) ? (acc1 * inv + b2[lane + 32]) : -BIGF;

    float mm = fmaxf(v0, v1);
    for (int o = 16; o; o >>= 1) mm = fmaxf(mm, __shfl_xor_sync(0xffffffffu, mm, o));
    float se = __expf(v0 - mm) + ((lane < 8) ? __expf(v1 - mm) : 0.f);
    for (int o = 16; o; o >>= 1) se += __shfl_xor_sync(0xffffffffu, se, o);
    float ls = mm + logf(se);
    out[(size_t)d * 40 + lane] = v0 - ls;
    if (lane < 8) out[(size_t)d * 40 + 32 + lane] = v1 - ls;
}

// ---------------- launch ----------------
extern "C" void kernel_launch(void* const* d_in, const int* in_sizes, int n_in,
                              void* d_out, int out_size) {
    const float* x   = (const float*)d_in[0];
    const void*  ei  = d_in[1];
    const float* W1  = (const float*)d_in[2];
    const float* as1 = (const float*)d_in[3];
    const float* ad1 = (const float*)d_in[4];
    const float* b1  = (const float*)d_in[5];
    const float* W2  = (const float*)d_in[6];
    const float* as2 = (const float*)d_in[7];
    const float* ad2 = (const float*)d_in[8];
    const float* b2  = (const float*)d_in[9];
    float* out = (float*)d_out;

    int N = in_sizes[0] / 128;
    int E = in_sizes[1] / 2;
    int NB = (N + 1023) / 1024;

    k_detect<<<1, 32>>>((const unsigned*)ei);
    k_convert<<<(E + 255) / 256, 256>>>(ei, E);
    k_init<<<(N + 255) / 256, 256>>>(N);
    k_hist<<<(E + 255) / 256, 256>>>(E);
    k_bsum<<<NB, 1024>>>(N);
    k_scanb<<<1, 128>>>(NB);
    k_scanf<<<NB, 1024>>>(N);
    k_scatter<<<(E + N + 255) / 256, 256>>>(E, N);

    k_gemm1<<<(N + 63) / 64, 256>>>(x, W1, N);
    k_att1<<<(N * 8 + 255) / 256, 256>>>(as1, ad1, N);
    k_agg1<<<(N + 7) / 8, 256>>>(b1, N);
    k_gemm2<<<(N + 63) / 64, 256>>>(W2, as2, ad2, N);
    k_agg2<<<(N + 7) / 8, 256>>>(b2, out, N);
}

// round 2
// speedup vs baseline: 1.1434x; 1.1434x over previous
#include <cuda_runtime.h>
#include <math.h>

#define NN 100000
#define EE 1600000
#define TEC (EE + NN)
#define BIGF 1e30f

// ---------------- scratch ----------------
__device__ float g_h1[NN * 64];
__device__ float g_out1[NN * 64];
__device__ float g_h2[NN * 40];
__device__ float g_a1s[NN * 8];
__device__ float g_a1d[NN * 8];
__device__ float g_a2s[NN];
__device__ float g_a2d[NN];
__device__ int   g_counts[NN];
__device__ int   g_rowptr[NN + 1];
__device__ int   g_cursor[NN];
__device__ int   g_src32[EE];
__device__ int   g_dst32[EE];
__device__ int   g_csr[TEC];
__device__ int   g_bsum[128];
__device__ int   g_flag;

// ---------------- edge dtype detection (int64 vs int32) ----------------
__global__ void k_detect(const unsigned* __restrict__ u) {
    int t = threadIdx.x;
    unsigned v = 0;
    for (int i = t; i < 128; i += 32) v |= u[2 * i + 1];
    unsigned any = __ballot_sync(0xffffffffu, v != 0u);
    if (t == 0) g_flag = (any == 0u) ? 1 : 0;
}

__global__ void k_init(int N) {
    int i = blockIdx.x * blockDim.x + threadIdx.x;
    if (i < N) g_counts[i] = 1;  // self-loop
}

// ---------------- fused convert + histogram (2 edges/thread, vector loads) ----
__global__ void k_edges(const void* __restrict__ ei, int E) {
    int idx = blockIdx.x * blockDim.x + threadIdx.x;
    int e = idx * 2;
    if (e >= E) return;
    int s0, s1, d0, d1;
    if (g_flag) {
        const longlong2* ps = (const longlong2*)ei;
        longlong2 sv = ps[idx];
        longlong2 dv = ps[(E >> 1) + idx];
        s0 = (int)sv.x; s1 = (int)sv.y;
        d0 = (int)dv.x; d1 = (int)dv.y;
    } else {
        const int2* ps = (const int2*)ei;
        int2 sv = ps[idx];
        int2 dv = ps[(E >> 1) + idx];
        s0 = sv.x; s1 = sv.y;
        d0 = dv.x; d1 = dv.y;
    }
    *(int2*)&g_src32[e] = make_int2(s0, s1);
    *(int2*)&g_dst32[e] = make_int2(d0, d1);
    atomicAdd(&g_counts[d0], 1);
    atomicAdd(&g_counts[d1], 1);
}

// ---------------- scans ----------------
__global__ void k_bsum(int N) {
    __shared__ int sm[1024];
    int i = blockIdx.x * 1024 + threadIdx.x;
    sm[threadIdx.x] = (i < N) ? g_counts[i] : 0;
    __syncthreads();
    for (int s = 512; s > 0; s >>= 1) {
        if (threadIdx.x < s) sm[threadIdx.x] += sm[threadIdx.x + s];
        __syncthreads();
    }
    if (threadIdx.x == 0) g_bsum[blockIdx.x] = sm[0];
}

__global__ void k_scanb(int nb) {
    __shared__ int sm[128];
    int t = threadIdx.x;
    int v = (t < nb) ? g_bsum[t] : 0;
    sm[t] = v;
    __syncthreads();
    for (int off = 1; off < 128; off <<= 1) {
        int u = (t >= off) ? sm[t - off] : 0;
        __syncthreads();
        sm[t] += u;
        __syncthreads();
    }
    if (t < nb) g_bsum[t] = sm[t] - v;
}

__global__ void k_scanf(int N) {
    __shared__ int sm[1024];
    int t = threadIdx.x;
    int i = blockIdx.x * 1024 + t;
    int v = (i < N) ? g_counts[i] : 0;
    sm[t] = v;
    __syncthreads();
    for (int off = 1; off < 1024; off <<= 1) {
        int u = (t >= off) ? sm[t - off] : 0;
        __syncthreads();
        sm[t] += u;
        __syncthreads();
    }
    int excl = sm[t] - v + g_bsum[blockIdx.x];
    if (i < N) { g_rowptr[i] = excl; g_cursor[i] = excl; }
    if (i == N - 1) g_rowptr[N] = excl + v;
}

__global__ void k_scatter(int E, int N) {
    int e = blockIdx.x * blockDim.x + threadIdx.x;
    if (e >= E + N) return;
    int s, d;
    if (e < E) { s = g_src32[e]; d = g_dst32[e]; }
    else       { s = e - E; d = s; }
    int pos = atomicAdd(&g_cursor[d], 1);
    g_csr[pos] = s;
}

// ---------------- GEMM1: h1 = x @ W1, fused attention scalars ----------------
__global__ void k_gemm1(const float* __restrict__ x, const float* __restrict__ W,
                        const float* __restrict__ as1, const float* __restrict__ ad1, int N) {
    __shared__ float xs[64][68];
    __shared__ float ws[64][68];
    int t = threadIdx.x;
    int r0 = blockIdx.x * 64;
    int tx = t & 15, ty = t >> 4;
    float acc[4][4];
#pragma unroll
    for (int i = 0; i < 4; ++i)
#pragma unroll
        for (int j = 0; j < 4; ++j) acc[i][j] = 0.f;

    for (int kt = 0; kt < 2; ++kt) {
#pragma unroll
        for (int p = 0; p < 4; ++p) {
            int row = ty + p * 16;
            int col4 = tx * 4;
            int gr = r0 + row;
            float4 v = make_float4(0.f, 0.f, 0.f, 0.f);
            if (gr < N) v = *(const float4*)&x[(size_t)gr * 128 + kt * 64 + col4];
            *(float4*)&xs[row][col4] = v;
            float4 wv = *(const float4*)&W[(size_t)(kt * 64 + row) * 64 + col4];
            *(float4*)&ws[row][col4] = wv;
        }
        __syncthreads();
#pragma unroll 16
        for (int k = 0; k < 64; ++k) {
            float4 b = *(const float4*)&ws[k][tx * 4];
            float a0 = xs[ty * 4 + 0][k];
            float a1 = xs[ty * 4 + 1][k];
            float a2 = xs[ty * 4 + 2][k];
            float a3 = xs[ty * 4 + 3][k];
            acc[0][0] += a0 * b.x; acc[0][1] += a0 * b.y; acc[0][2] += a0 * b.z; acc[0][3] += a0 * b.w;
            acc[1][0] += a1 * b.x; acc[1][1] += a1 * b.y; acc[1][2] += a1 * b.z; acc[1][3] += a1 * b.w;
            acc[2][0] += a2 * b.x; acc[2][1] += a2 * b.y; acc[2][2] += a2 * b.z; acc[2][3] += a2 * b.w;
            acc[3][0] += a3 * b.x; acc[3][1] += a3 * b.y; acc[3][2] += a3 * b.z; acc[3][3] += a3 * b.w;
        }
        __syncthreads();
    }
    // att coefficients for this thread's 4 columns (flat col = head*8 + c)
    float4 asv = *(const float4*)&as1[tx * 4];
    float4 adv = *(const float4*)&ad1[tx * 4];
#pragma unroll
    for (int i = 0; i < 4; ++i) {
        int gr = r0 + ty * 4 + i;
        float ps = acc[i][0] * asv.x + acc[i][1] * asv.y + acc[i][2] * asv.z + acc[i][3] * asv.w;
        float pd = acc[i][0] * adv.x + acc[i][1] * adv.y + acc[i][2] * adv.z + acc[i][3] * adv.w;
        ps += __shfl_xor_sync(0xffffffffu, ps, 1);
        pd += __shfl_xor_sync(0xffffffffu, pd, 1);
        if (gr < N) {
            *(float4*)&g_h1[(size_t)gr * 64 + tx * 4] =
                make_float4(acc[i][0], acc[i][1], acc[i][2], acc[i][3]);
            if (!(tx & 1)) {
                g_a1s[(size_t)gr * 8 + (tx >> 1)] = ps;
                g_a1d[(size_t)gr * 8 + (tx >> 1)] = pd;
            }
        }
    }
}

// ---------------- layer-1 softmax + aggregation (single pass, no max) --------
__global__ void k_agg1(const float* __restrict__ b1, int N) {
    int warp = threadIdx.x >> 5;
    int lane = threadIdx.x & 31;
    int d = blockIdx.x * 8 + warp;
    if (d >= N) return;
    int rs = g_rowptr[d], re = g_rowptr[d + 1];
    int h = lane & 7;
    float adst = g_a1d[(size_t)d * 8 + h];
    int hs0 = lane >> 3, hs1 = hs0 + 4;

    float wsum = 0.f, acc0 = 0.f, acc1 = 0.f;
    int i = rs;
    for (; i + 1 < re; i += 2) {
        int s0 = __ldg(&g_csr[i]);
        int s1 = __ldg(&g_csr[i + 1]);
        float e0 = __ldg(&g_a1s[(size_t)s0 * 8 + h]) + adst;
        float e1 = __ldg(&g_a1s[(size_t)s1 * 8 + h]) + adst;
        e0 = (e0 > 0.f) ? e0 : 0.2f * e0;
        e1 = (e1 > 0.f) ? e1 : 0.2f * e1;
        float w0 = __expf(e0);
        float w1 = __expf(e1);
        wsum += w0 + w1;
        float wa0 = __shfl_sync(0xffffffffu, w0, hs0);
        float wb0 = __shfl_sync(0xffffffffu, w0, hs1);
        float wa1 = __shfl_sync(0xffffffffu, w1, hs0);
        float wb1 = __shfl_sync(0xffffffffu, w1, hs1);
        const float* hp0 = &g_h1[(size_t)s0 * 64];
        const float* hp1 = &g_h1[(size_t)s1 * 64];
        float f00 = __ldg(&hp0[lane]);
        float f01 = __ldg(&hp0[lane + 32]);
        float f10 = __ldg(&hp1[lane]);
        float f11 = __ldg(&hp1[lane + 32]);
        acc0 += wa0 * f00 + wa1 * f10;
        acc1 += wb0 * f01 + wb1 * f11;
    }
    if (i < re) {
        int s = __ldg(&g_csr[i]);
        float e = __ldg(&g_a1s[(size_t)s * 8 + h]) + adst;
        e = (e > 0.f) ? e : 0.2f * e;
        float w = __expf(e);
        wsum += w;
        float wa = __shfl_sync(0xffffffffu, w, hs0);
        float wb = __shfl_sync(0xffffffffu, w, hs1);
        const float* hp = &g_h1[(size_t)s * 64];
        acc0 += wa * __ldg(&hp[lane]);
        acc1 += wb * __ldg(&hp[lane + 32]);
    }
    float d0 = __shfl_sync(0xffffffffu, wsum, hs0);
    float d1 = __shfl_sync(0xffffffffu, wsum, hs1);
    float o0 = acc0 / d0 + b1[lane];
    float o1 = acc1 / d1 + b1[lane + 32];
    o0 = (o0 > 0.f) ? o0 : (__expf(o0) - 1.f);
    o1 = (o1 > 0.f) ? o1 : (__expf(o1) - 1.f);
    g_out1[(size_t)d * 64 + lane] = o0;
    g_out1[(size_t)d * 64 + lane + 32] = o1;
}

// ---------------- GEMM2 + fused att2 ----------------
__global__ void k_gemm2(const float* __restrict__ W2, const float* __restrict__ as2,
                        const float* __restrict__ ad2, int N) {
    __shared__ float xs[64][68];
    __shared__ float ws[64][40];
    __shared__ float sa[40], sd[40];
    int t = threadIdx.x;
    int r0 = blockIdx.x * 64;
    for (int i = t; i < 64 * 40; i += 256) ws[i / 40][i % 40] = W2[i];
    if (t < 40) { sa[t] = as2[t]; sd[t] = ad2[t]; }
#pragma unroll
    for (int p = 0; p < 4; ++p) {
        int idx = t + p * 256;
        int row = idx >> 4;
        int col4 = (idx & 15) * 4;
        int gr = r0 + row;
        float4 v = make_float4(0.f, 0.f, 0.f, 0.f);
        if (gr < N) v = *(const float4*)&g_out1[(size_t)gr * 64 + col4];
        *(float4*)&xs[row][col4] = v;
    }
    __syncthreads();
    int row = t >> 2, g = t & 3;
    int gr = r0 + row;
    float acc[10];
#pragma unroll
    for (int j = 0; j < 10; ++j) acc[j] = 0.f;
#pragma unroll 8
    for (int k = 0; k < 64; ++k) {
        float a = xs[row][k];
#pragma unroll
        for (int j = 0; j < 10; ++j) acc[j] += a * ws[k][g * 10 + j];
    }
    float ps = 0.f, pd = 0.f;
    if (gr < N) {
#pragma unroll
        for (int j = 0; j < 10; ++j) {
            g_h2[(size_t)gr * 40 + g * 10 + j] = acc[j];
            ps += acc[j] * sa[g * 10 + j];
            pd += acc[j] * sd[g * 10 + j];
        }
    }
    ps += __shfl_xor_sync(0xffffffffu, ps, 1);
    ps += __shfl_xor_sync(0xffffffffu, ps, 2);
    pd += __shfl_xor_sync(0xffffffffu, pd, 1);
    pd += __shfl_xor_sync(0xffffffffu, pd, 2);
    if (g == 0 && gr < N) { g_a2s[gr] = ps; g_a2d[gr] = pd; }
}

// ---------------- layer-2 softmax + aggregation + log_softmax (single pass) --
__global__ void k_agg2(const float* __restrict__ b2, float* __restrict__ out, int N) {
    int warp = threadIdx.x >> 5, lane = threadIdx.x & 31;
    int d = blockIdx.x * 8 + warp;
    if (d >= N) return;
    int rs = g_rowptr[d], re = g_rowptr[d + 1];
    float adst = g_a2d[d];

    float wsum = 0.f, acc0 = 0.f, acc1 = 0.f;
    int i = rs;
    for (; i + 1 < re; i += 2) {
        int s0 = __ldg(&g_csr[i]);
        int s1 = __ldg(&g_csr[i + 1]);
        float e0 = __ldg(&g_a2s[s0]) + adst;
        float e1 = __ldg(&g_a2s[s1]) + adst;
        e0 = (e0 > 0.f) ? e0 : 0.2f * e0;
        e1 = (e1 > 0.f) ? e1 : 0.2f * e1;
        float w0 = __expf(e0);
        float w1 = __expf(e1);
        wsum += w0 + w1;
        const float* hp0 = &g_h2[(size_t)s0 * 40];
        const float* hp1 = &g_h2[(size_t)s1 * 40];
        float f00 = __ldg(&hp0[lane]);
        float f10 = __ldg(&hp1[lane]);
        acc0 += w0 * f00 + w1 * f10;
        if (lane < 8) {
            acc1 += w0 * __ldg(&hp0[lane + 32]) + w1 * __ldg(&hp1[lane + 32]);
        }
    }
    if (i < re) {
        int s = __ldg(&g_csr[i]);
        float e = __ldg(&g_a2s[s]) + adst;
        e = (e > 0.f) ? e : 0.2f * e;
        float w = __expf(e);
        wsum += w;
        const float* hp = &g_h2[(size_t)s * 40];
        acc0 += w * __ldg(&hp[lane]);
        if (lane < 8) acc1 += w * __ldg(&hp[lane + 32]);
    }
    float inv = 1.f / wsum;
    float v0 = acc0 * inv + b2[lane];
    float v1 = (lane < 8) ? (acc1 * inv + b2[lane + 32]) : -BIGF;

    float mm = fmaxf(v0, v1);
    for (int o = 16; o; o >>= 1) mm = fmaxf(mm, __shfl_xor_sync(0xffffffffu, mm, o));
    float se = __expf(v0 - mm) + ((lane < 8) ? __expf(v1 - mm) : 0.f);
    for (int o = 16; o; o >>= 1) se += __shfl_xor_sync(0xffffffffu, se, o);
    float ls = mm + logf(se);
    out[(size_t)d * 40 + lane] = v0 - ls;
    if (lane < 8) out[(size_t)d * 40 + 32 + lane] = v1 - ls;
}

// ---------------- launch ----------------
extern "C" void kernel_launch(void* const* d_in, const int* in_sizes, int n_in,
                              void* d_out, int out_size) {
    const float* x   = (const float*)d_in[0];
    const void*  ei  = d_in[1];
    const float* W1  = (const float*)d_in[2];
    const float* as1 = (const float*)d_in[3];
    const float* ad1 = (const float*)d_in[4];
    const float* b1  = (const float*)d_in[5];
    const float* W2  = (const float*)d_in[6];
    const float* as2 = (const float*)d_in[7];
    const float* ad2 = (const float*)d_in[8];
    const float* b2  = (const float*)d_in[9];
    float* out = (float*)d_out;

    int N = in_sizes[0] / 128;
    int E = in_sizes[1] / 2;
    int NB = (N + 1023) / 1024;

    k_detect<<<1, 32>>>((const unsigned*)ei);
    k_init<<<(N + 255) / 256, 256>>>(N);
    k_edges<<<(E / 2 + 255) / 256, 256>>>(ei, E);
    k_bsum<<<NB, 1024>>>(N);
    k_scanb<<<1, 128>>>(NB);
    k_scanf<<<NB, 1024>>>(N);
    k_scatter<<<(E + N + 255) / 256, 256>>>(E, N);

    k_gemm1<<<(N + 63) / 64, 256>>>(x, W1, as1, ad1, N);
    k_agg1<<<(N + 7) / 8, 256>>>(b1, N);
    k_gemm2<<<(N + 63) / 64, 256>>>(W2, as2, ad2, N);
    k_agg2<<<(N + 7) / 8, 256>>>(b2, out, N);
}